// round 5
// baseline (speedup 1.0000x reference)
#include <cuda_runtime.h>
#include <cuda_bf16.h>

#define NROWS 16384          // B*S
#define DIMV  512
#define NQ    8
#define NK    1024
#define NDTOT (NROWS*DIMV)   // 8388608
#define NETOT (NQ*NK*DIMV)   // 4194304

// ------------------------- device scratch (no allocs) ----------------------
__device__ float  g_res[NDTOT];            // fp32 residual
__device__ float  g_enorm[NQ*NK];          // ||e||^2 fp32
__device__ int    g_semax[NQ];             // max ||e||^2 bits per step
__device__ float  g_rnorm[NROWS];          // per-row ||r||^2 (for margin)
__device__ double g_loss_part[NQ*512];     // loss partials
__device__ float  g_coarse[(size_t)NROWS*NK];   // coarse distances, 64MB
// bf16 high-limbs only
__device__ uint4  g_rh[NDTOT/8];
__device__ uint4  g_eh[NETOT/8];

// ------------------------- PTX helpers (sm_80-compatible only) --------------
__device__ __forceinline__ unsigned smem_u32(const void* p) {
    unsigned a;
    asm("{ .reg .u64 t; cvta.to.shared.u64 t, %1; cvt.u32.u64 %0, t; }"
        : "=r"(a) : "l"(p));
    return a;
}
__device__ __forceinline__ void ldsm4(unsigned* r, unsigned addr) {
    asm volatile("ldmatrix.sync.aligned.m8n8.x4.shared.b16 {%0,%1,%2,%3}, [%4];"
        : "=r"(r[0]), "=r"(r[1]), "=r"(r[2]), "=r"(r[3]) : "r"(addr));
}
__device__ __forceinline__ void mma16816(float* c, const unsigned* a,
                                         unsigned b0, unsigned b1) {
    asm volatile(
        "mma.sync.aligned.m16n8k16.row.col.f32.bf16.bf16.f32 "
        "{%0,%1,%2,%3}, {%4,%5,%6,%7}, {%8,%9}, {%0,%1,%2,%3};"
        : "+f"(c[0]), "+f"(c[1]), "+f"(c[2]), "+f"(c[3])
        : "r"(a[0]), "r"(a[1]), "r"(a[2]), "r"(a[3]), "r"(b0), "r"(b1));
}
__device__ __forceinline__ unsigned short bf16h(float v) {
    __nv_bfloat16 b = __float2bfloat16(v);
    return *reinterpret_cast<unsigned short*>(&b);
}
__device__ __forceinline__ uint2 packh4(float x, float y, float z, float w) {
    return make_uint2((unsigned)bf16h(x) | ((unsigned)bf16h(y) << 16),
                      (unsigned)bf16h(z) | ((unsigned)bf16h(w) << 16));
}

// ------------------------- setup kernels -------------------------------------
// One warp per row: copy x->res, bf16 high limb, per-row ||x||^2.
__global__ void copy_row_kernel(const float* __restrict__ x) {
    const int lane = threadIdx.x & 31;
    const int wid  = threadIdx.x >> 5;
    const int row  = blockIdx.x * 8 + wid;
    const float4* xp = reinterpret_cast<const float4*>(x) + (size_t)row * 128;
    float4* rp = reinterpret_cast<float4*>(g_res) + (size_t)row * 128;
    uint2*  hp = reinterpret_cast<uint2*>(g_rh) + (size_t)row * 128;
    double ns = 0.0;
    #pragma unroll
    for (int j = 0; j < 4; ++j) {
        const int li = lane + 32 * j;
        float4 v = xp[li];
        rp[li] = v;
        hp[li] = packh4(v.x, v.y, v.z, v.w);
        ns += (double)v.x*v.x + (double)v.y*v.y + (double)v.z*v.z + (double)v.w*v.w;
    }
    #pragma unroll
    for (int off = 16; off > 0; off >>= 1)
        ns += __shfl_down_sync(0xffffffffu, ns, off);
    if (lane == 0) g_rnorm[row] = (float)ns;
}

__global__ void split_emb_kernel(const float* __restrict__ emb) {
    int i = blockIdx.x * blockDim.x + threadIdx.x;       // 0..1048575
    float4 v = reinterpret_cast<const float4*>(emb)[i];
    reinterpret_cast<uint2*>(g_eh)[i] = packh4(v.x, v.y, v.z, v.w);
}

__global__ void enorm_kernel(const float* __restrict__ emb) {
    int gwarp = (blockIdx.x * blockDim.x + threadIdx.x) >> 5;  // 0..8191
    int lane  = threadIdx.x & 31;
    const float* e = emb + (size_t)gwarp * DIMV;
    float s = 0.f;
    #pragma unroll
    for (int d = lane; d < DIMV; d += 32) { float v = e[d]; s += v * v; }
    #pragma unroll
    for (int off = 16; off > 0; off >>= 1)
        s += __shfl_down_sync(0xffffffffu, s, off);
    if (lane == 0) {
        g_enorm[gwarp] = s;
        atomicMax(&g_semax[gwarp >> 10], __float_as_int(s));   // s > 0
    }
}

// ------------------------- Phase A: hh coarse GEMM ---------------------------
// 128 CTAs x 256 threads. CTA owns 128 rows; A-tile (128x512 bf16 = 128KB)
// loaded once as 8 ktile slabs; B streamed in 64 stages (chunk*8+kt) through a
// 4-stage 16KB ring. Writes coarse dist = en - 2*acc for all 1024 codes.
__global__ void __launch_bounds__(256, 1) dist_hh_kernel(int q) {
    extern __shared__ __align__(16) char dsm_raw[];
    const int tid  = threadIdx.x;
    const int lane = tid & 31;
    const int wid  = tid >> 5;
    const int mw = wid & 3, nw = wid >> 2;
    const int rowBase = blockIdx.x << 7;

    unsigned rawb = smem_u32(dsm_raw);
    unsigned dynb = (rawb + 1023u) & ~1023u;
    const unsigned Bbase = dynb + 131072u;

    const int g = lane >> 2, tig = lane & 3;
    const int rlo = lane & 15, kh = lane >> 4;
    const int mwBase = mw * 32, nwBase = nw * 64;
    const int aSw[2] = { ((mwBase +  0 + rlo) & 7) << 4,
                         ((mwBase + 16 + rlo) & 7) << 4 };
    const int bSw[4] = { ((nwBase +  0 + rlo) & 7) << 4,
                         ((nwBase + 16 + rlo) & 7) << 4,
                         ((nwBase + 32 + rlo) & 7) << 4,
                         ((nwBase + 48 + rlo) & 7) << 4 };
    const int aRow[2] = { (mwBase +  0 + rlo) * 128, (mwBase + 16 + rlo) * 128 };
    const int bRow[4] = { (nwBase +  0 + rlo) * 128, (nwBase + 16 + rlo) * 128,
                          (nwBase + 32 + rlo) * 128, (nwBase + 48 + rlo) * 128 };

    // ---- load A (rows' hh limbs): 8 ktiles x 16KB ----
    #pragma unroll
    for (int j = 0; j < 32; ++j) {
        const int u = tid + (j << 8);                 // 0..8191 (16B units)
        const int kt = u >> 10, within = u & 1023;
        const int row = within >> 3, seg = within & 7;
        const uint4* src = g_rh + (size_t)(rowBase + row) * 64 + kt * 8 + seg;
        const unsigned dst = dynb + kt * 16384 + row * 128
                           + ((seg * 16) ^ ((row & 7) << 4));
        asm volatile("cp.async.cg.shared.global [%0], [%1], 16;"
                     :: "r"(dst), "l"(src));
    }
    asm volatile("cp.async.commit_group;" ::: "memory");

    // ---- B stage issuer: stage s -> chunk s>>3, ktile s&7 ----
    const int ebase = q * NK;
    auto issueB = [&](int s) {
        const int chunkI = s >> 3, ktI = s & 7;
        const unsigned buf = Bbase + (unsigned)(s & 3) * 16384u;
        #pragma unroll
        for (int j = 0; j < 4; ++j) {
            const int u = tid + (j << 8);             // 0..1023
            const int row = u >> 3, seg = u & 7;
            const uint4* src = g_eh + (size_t)(ebase + chunkI * 128 + row) * 64
                             + ktI * 8 + seg;
            const unsigned dst = buf + row * 128
                               + ((seg * 16) ^ ((row & 7) << 4));
            asm volatile("cp.async.cg.shared.global [%0], [%1], 16;"
                         :: "r"(dst), "l"(src));
        }
    };
    #pragma unroll
    for (int p = 0; p < 3; ++p) {
        issueB(p);
        asm volatile("cp.async.commit_group;" ::: "memory");
    }

    for (int chunk = 0; chunk < 8; ++chunk) {
        float c[2][8][4];
        #pragma unroll
        for (int mi = 0; mi < 2; ++mi)
            #pragma unroll
            for (int nj = 0; nj < 8; ++nj)
                #pragma unroll
                for (int k = 0; k < 4; ++k) c[mi][nj][k] = 0.f;

        for (int kt = 0; kt < 8; ++kt) {
            const int s = chunk * 8 + kt;
            asm volatile("cp.async.wait_group 2;" ::: "memory");
            __syncthreads();
            if (s + 3 < 64) issueB(s + 3);
            asm volatile("cp.async.commit_group;" ::: "memory");

            const unsigned Akt = dynb + kt * 16384;
            const unsigned stg = Bbase + (unsigned)(s & 3) * 16384u;
            #pragma unroll
            for (int k0b = 0; k0b < 4; ++k0b) {
                const int colb = k0b * 32 + kh * 16;
                unsigned Af[2][4], Bf[4][4];
                #pragma unroll
                for (int mi = 0; mi < 2; ++mi)
                    ldsm4(Af[mi], Akt + aRow[mi] + (colb ^ aSw[mi]));
                #pragma unroll
                for (int njp = 0; njp < 4; ++njp)
                    ldsm4(Bf[njp], stg + bRow[njp] + (colb ^ bSw[njp]));
                #pragma unroll
                for (int mi = 0; mi < 2; ++mi)
                    #pragma unroll
                    for (int nj = 0; nj < 8; ++nj)
                        mma16816(c[mi][nj], Af[mi],
                                 Bf[nj >> 1][nj & 1], Bf[nj >> 1][2 + (nj & 1)]);
            }
            __syncthreads();
        }

        // write coarse distances
        const float* __restrict__ enp = g_enorm + q * NK + chunk * 128;
        #pragma unroll
        for (int mi = 0; mi < 2; ++mi)
            #pragma unroll
            for (int rh = 0; rh < 2; ++rh) {
                const int row = rowBase + mwBase + mi * 16 + rh * 8 + g;
                float* dst = g_coarse + (size_t)row * NK + chunk * 128;
                #pragma unroll
                for (int nj = 0; nj < 8; ++nj) {
                    const int colL = nwBase + nj * 8 + 2 * tig;
                    float2 d2;
                    d2.x = fmaf(-2.f, c[mi][nj][rh * 2 + 0], enp[colL + 0]);
                    d2.y = fmaf(-2.f, c[mi][nj][rh * 2 + 1], enp[colL + 1]);
                    *reinterpret_cast<float2*>(dst + colL) = d2;
                }
            }
    }
}

// ------------------------- Phase B: rescore + update ------------------------
// 512 CTAs x 256 threads; warp handles 4 rows. Candidates within deterministic
// margin of coarse min get exact double-precision rescore; then fused update.
__global__ void __launch_bounds__(256) rescore_update_kernel(
    const float* __restrict__ E, float* __restrict__ outF, int q)
{
    __shared__ int    sCand[8][64];
    __shared__ int    sCnt[8];
    __shared__ double sLoss[8];

    const int tid  = threadIdx.x;
    const int lane = tid & 31;
    const int wid  = tid >> 5;

    const float semax = sqrtf(__int_as_float(g_semax[q]));
    double lossAcc = 0.0;

    for (int rr = 0; rr < 4; ++rr) {
        const int row = blockIdx.x * 32 + wid * 4 + rr;
        const float4* cd4 =
            reinterpret_cast<const float4*>(g_coarse + (size_t)row * NK);

        // pass 1: coarse min
        float vmin = 3.4e38f;
        #pragma unroll
        for (int i = 0; i < 8; ++i) {
            const float4 d4 = cd4[i * 32 + lane];
            vmin = fminf(vmin, fminf(fminf(d4.x, d4.y), fminf(d4.z, d4.w)));
        }
        #pragma unroll
        for (int off = 16; off > 0; off >>= 1)
            vmin = fminf(vmin, __shfl_xor_sync(0xffffffffu, vmin, off));

        const float margin = 0.022f * sqrtf(g_rnorm[row]) * semax;
        const float thr = vmin + margin;

        if (lane == 0) sCnt[wid] = 0;
        __syncwarp();
        // pass 2: collect candidates
        #pragma unroll
        for (int i = 0; i < 8; ++i) {
            const float4 d4 = cd4[i * 32 + lane];
            const int cb = i * 128 + lane * 4;
            if (d4.x <= thr) { int p = atomicAdd(&sCnt[wid], 1); if (p < 64) sCand[wid][p] = cb + 0; }
            if (d4.y <= thr) { int p = atomicAdd(&sCnt[wid], 1); if (p < 64) sCand[wid][p] = cb + 1; }
            if (d4.z <= thr) { int p = atomicAdd(&sCnt[wid], 1); if (p < 64) sCand[wid][p] = cb + 2; }
            if (d4.w <= thr) { int p = atomicAdd(&sCnt[wid], 1); if (p < 64) sCand[wid][p] = cb + 3; }
        }
        __syncwarp();
        const int cnt = sCnt[wid];
        const bool full = (cnt > 64);
        const int ncand = full ? NK : cnt;

        const float4* rp = reinterpret_cast<const float4*>(g_res + (size_t)row * DIMV);
        double bestD = 1.0e300;
        int    bestI = 0x7fffffff;
        for (int k = 0; k < ncand; ++k) {
            const int col = full ? k : sCand[wid][k];
            const float4* ep = reinterpret_cast<const float4*>(E + (size_t)col * DIMV);
            double acc = 0.0;
            #pragma unroll
            for (int j = 0; j < 4; ++j) {
                const float4 a = rp[lane + 32 * j];
                const float4 b = ep[lane + 32 * j];
                acc += (double)a.x * b.x + (double)a.y * b.y
                     + (double)a.z * b.z + (double)a.w * b.w;
            }
            #pragma unroll
            for (int off = 16; off > 0; off >>= 1)
                acc += __shfl_xor_sync(0xffffffffu, acc, off);
            const double dex = (double)g_enorm[q * NK + col] - 2.0 * acc;
            if (dex < bestD || (dex == bestD && col < bestI)) {
                bestD = dex; bestI = col;
            }
        }

        // fused update: r -= e[best]; refresh h-limb; norms
        const float4* eb = reinterpret_cast<const float4*>(E + (size_t)bestI * DIMV);
        float4* rw = reinterpret_cast<float4*>(g_res + (size_t)row * DIMV);
        uint2*  hw = reinterpret_cast<uint2*>(g_rh) + (size_t)row * 128;
        double ns = 0.0;
        #pragma unroll
        for (int j = 0; j < 4; ++j) {
            const int li = lane + 32 * j;
            float4 r = rw[li];
            const float4 e = eb[li];
            r.x -= e.x; r.y -= e.y; r.z -= e.z; r.w -= e.w;
            rw[li] = r;
            hw[li] = packh4(r.x, r.y, r.z, r.w);
            ns += (double)r.x * r.x + (double)r.y * r.y
                + (double)r.z * r.z + (double)r.w * r.w;
        }
        #pragma unroll
        for (int off = 16; off > 0; off >>= 1)
            ns += __shfl_xor_sync(0xffffffffu, ns, off);
        if (lane == 0) {
            g_rnorm[row] = (float)ns;
            lossAcc += ns;
            outF[NDTOT + (size_t)row * NQ + q] = (float)bestI;
        }
    }

    if (lane == 0) sLoss[wid] = lossAcc;
    __syncthreads();
    if (tid == 0) {
        double tot = 0.0;
        #pragma unroll
        for (int w = 0; w < 8; ++w) tot += sLoss[w];
        g_loss_part[q * 512 + blockIdx.x] = tot;
    }
}

// ------------------------- finalize -----------------------------------------
__global__ void finalize_kernel(const float* __restrict__ x,
                                float* __restrict__ outF)
{
    const int i = blockIdx.x * blockDim.x + threadIdx.x;
    const float4 xv = reinterpret_cast<const float4*>(x)[i];
    const float4 rv = reinterpret_cast<const float4*>(g_res)[i];
    float4 o;
    o.x = xv.x - rv.x; o.y = xv.y - rv.y;
    o.z = xv.z - rv.z; o.w = xv.w - rv.w;
    reinterpret_cast<float4*>(outF)[i] = o;

    if (blockIdx.x == 0 && threadIdx.x == 0) {
        double tot = 0.0;
        for (int k = 0; k < NQ * 512; ++k) tot += g_loss_part[k];
        outF[NDTOT + (size_t)NROWS * NQ] = (float)(2.0 * tot / (double)NDTOT);
    }
}

// ---------------------------------------------------------------------------
extern "C" void kernel_launch(void* const* d_in, const int* in_sizes, int n_in,
                              void* d_out, int out_size)
{
    const float* x   = (const float*)d_in[0];
    const float* emb = (const float*)d_in[1];
    float* outF = (float*)d_out;

    cudaFuncSetAttribute(dist_hh_kernel,
                         cudaFuncAttributeMaxDynamicSharedMemorySize, 197632);

    copy_row_kernel<<<2048, 256>>>(x);
    split_emb_kernel<<<4096, 256>>>(emb);
    enorm_kernel<<<1024, 256>>>(emb);

    for (int q = 0; q < NQ; ++q) {
        const float* Eq = emb + (size_t)q * NK * DIMV;
        dist_hh_kernel<<<128, 256, 197632>>>(q);
        rescore_update_kernel<<<512, 256>>>(Eq, outF, q);
    }

    finalize_kernel<<<8192, 256>>>(x, outF);
}

// round 9
// speedup vs baseline: 1.9996x; 1.9996x over previous
#include <cuda_runtime.h>
#include <cuda_bf16.h>

#define NROWS 16384          // B*S
#define DIMV  512
#define NQ    8
#define NK    1024
#define NDTOT (NROWS*DIMV)   // 8388608
#define NETOT (NQ*NK*DIMV)   // 4194304

// ------------------------- device scratch (no allocs) ----------------------
__device__ float  g_res[NDTOT];            // fp32 residual
__device__ float  g_enorm[NQ*NK];          // ||e||^2 fp32
__device__ int    g_semax[NQ];             // max ||e||^2 bits per step
__device__ float  g_rnorm[NROWS];          // per-row ||r||^2 (for margin)
__device__ float  g_cmin[NROWS];           // per-row coarse min
__device__ double g_loss_part[NQ*2048];    // loss partials
__device__ float  g_coarse[(size_t)NROWS*NK];   // coarse distances, 64MB
// bf16 high-limbs only
__device__ uint4  g_rh[NDTOT/8];
__device__ uint4  g_eh[NETOT/8];

// ------------------------- PTX helpers (sm_80-compatible only) --------------
__device__ __forceinline__ unsigned smem_u32(const void* p) {
    unsigned a;
    asm("{ .reg .u64 t; cvta.to.shared.u64 t, %1; cvt.u32.u64 %0, t; }"
        : "=r"(a) : "l"(p));
    return a;
}
__device__ __forceinline__ void ldsm4(unsigned* r, unsigned addr) {
    asm volatile("ldmatrix.sync.aligned.m8n8.x4.shared.b16 {%0,%1,%2,%3}, [%4];"
        : "=r"(r[0]), "=r"(r[1]), "=r"(r[2]), "=r"(r[3]) : "r"(addr));
}
__device__ __forceinline__ void mma16816(float* c, const unsigned* a,
                                         unsigned b0, unsigned b1) {
    asm volatile(
        "mma.sync.aligned.m16n8k16.row.col.f32.bf16.bf16.f32 "
        "{%0,%1,%2,%3}, {%4,%5,%6,%7}, {%8,%9}, {%0,%1,%2,%3};"
        : "+f"(c[0]), "+f"(c[1]), "+f"(c[2]), "+f"(c[3])
        : "r"(a[0]), "r"(a[1]), "r"(a[2]), "r"(a[3]), "r"(b0), "r"(b1));
}
__device__ __forceinline__ unsigned short bf16h(float v) {
    __nv_bfloat16 b = __float2bfloat16(v);
    return *reinterpret_cast<unsigned short*>(&b);
}
__device__ __forceinline__ uint2 packh4(float x, float y, float z, float w) {
    return make_uint2((unsigned)bf16h(x) | ((unsigned)bf16h(y) << 16),
                      (unsigned)bf16h(z) | ((unsigned)bf16h(w) << 16));
}

// ------------------------- setup kernels -------------------------------------
__global__ void copy_row_kernel(const float* __restrict__ x) {
    const int lane = threadIdx.x & 31;
    const int wid  = threadIdx.x >> 5;
    const int row  = blockIdx.x * 8 + wid;
    const float4* xp = reinterpret_cast<const float4*>(x) + (size_t)row * 128;
    float4* rp = reinterpret_cast<float4*>(g_res) + (size_t)row * 128;
    uint2*  hp = reinterpret_cast<uint2*>(g_rh) + (size_t)row * 128;
    float ns = 0.f;
    #pragma unroll
    for (int j = 0; j < 4; ++j) {
        const int li = lane + 32 * j;
        float4 v = xp[li];
        rp[li] = v;
        hp[li] = packh4(v.x, v.y, v.z, v.w);
        ns += v.x*v.x + v.y*v.y + v.z*v.z + v.w*v.w;
    }
    #pragma unroll
    for (int off = 16; off > 0; off >>= 1)
        ns += __shfl_xor_sync(0xffffffffu, ns, off);
    if (lane == 0) g_rnorm[row] = ns;
}

__global__ void split_emb_kernel(const float* __restrict__ emb) {
    int i = blockIdx.x * blockDim.x + threadIdx.x;       // 0..1048575
    float4 v = reinterpret_cast<const float4*>(emb)[i];
    reinterpret_cast<uint2*>(g_eh)[i] = packh4(v.x, v.y, v.z, v.w);
}

__global__ void enorm_kernel(const float* __restrict__ emb) {
    int gwarp = (blockIdx.x * blockDim.x + threadIdx.x) >> 5;  // 0..8191
    int lane  = threadIdx.x & 31;
    const float* e = emb + (size_t)gwarp * DIMV;
    float s = 0.f;
    #pragma unroll
    for (int d = lane; d < DIMV; d += 32) { float v = e[d]; s += v * v; }
    #pragma unroll
    for (int off = 16; off > 0; off >>= 1)
        s += __shfl_down_sync(0xffffffffu, s, off);
    if (lane == 0) {
        g_enorm[gwarp] = s;
        atomicMax(&g_semax[gwarp >> 10], __float_as_int(s));   // s > 0
    }
}

// ------------------------- Phase A: hh coarse GEMM + per-row coarse min ------
__global__ void __launch_bounds__(256, 1) dist_hh_kernel(int q) {
    extern __shared__ __align__(16) char dsm_raw[];
    __shared__ float sMin[128][2];

    const int tid  = threadIdx.x;
    const int lane = tid & 31;
    const int wid  = tid >> 5;
    const int mw = wid & 3, nw = wid >> 2;
    const int rowBase = blockIdx.x << 7;

    unsigned rawb = smem_u32(dsm_raw);
    unsigned dynb = (rawb + 1023u) & ~1023u;
    const unsigned Bbase = dynb + 131072u;

    const int g = lane >> 2, tig = lane & 3;
    const int rlo = lane & 15, kh = lane >> 4;
    const int mwBase = mw * 32, nwBase = nw * 64;
    const int aSw[2] = { ((mwBase +  0 + rlo) & 7) << 4,
                         ((mwBase + 16 + rlo) & 7) << 4 };
    const int bSw[4] = { ((nwBase +  0 + rlo) & 7) << 4,
                         ((nwBase + 16 + rlo) & 7) << 4,
                         ((nwBase + 32 + rlo) & 7) << 4,
                         ((nwBase + 48 + rlo) & 7) << 4 };
    const int aRow[2] = { (mwBase +  0 + rlo) * 128, (mwBase + 16 + rlo) * 128 };
    const int bRow[4] = { (nwBase +  0 + rlo) * 128, (nwBase + 16 + rlo) * 128,
                          (nwBase + 32 + rlo) * 128, (nwBase + 48 + rlo) * 128 };

    // ---- load A (rows' hh limbs): 8 ktiles x 16KB ----
    #pragma unroll
    for (int j = 0; j < 32; ++j) {
        const int u = tid + (j << 8);                 // 0..8191 (16B units)
        const int kt = u >> 10, within = u & 1023;
        const int row = within >> 3, seg = within & 7;
        const uint4* src = g_rh + (size_t)(rowBase + row) * 64 + kt * 8 + seg;
        const unsigned dst = dynb + kt * 16384 + row * 128
                           + ((seg * 16) ^ ((row & 7) << 4));
        asm volatile("cp.async.cg.shared.global [%0], [%1], 16;"
                     :: "r"(dst), "l"(src));
    }
    asm volatile("cp.async.commit_group;" ::: "memory");

    const int ebase = q * NK;
    auto issueB = [&](int s) {
        const int chunkI = s >> 3, ktI = s & 7;
        const unsigned buf = Bbase + (unsigned)(s & 3) * 16384u;
        #pragma unroll
        for (int j = 0; j < 4; ++j) {
            const int u = tid + (j << 8);             // 0..1023
            const int row = u >> 3, seg = u & 7;
            const uint4* src = g_eh + (size_t)(ebase + chunkI * 128 + row) * 64
                             + ktI * 8 + seg;
            const unsigned dst = buf + row * 128
                               + ((seg * 16) ^ ((row & 7) << 4));
            asm volatile("cp.async.cg.shared.global [%0], [%1], 16;"
                         :: "r"(dst), "l"(src));
        }
    };
    #pragma unroll
    for (int p = 0; p < 3; ++p) {
        issueB(p);
        asm volatile("cp.async.commit_group;" ::: "memory");
    }

    float vb[2][2];
    vb[0][0] = vb[0][1] = vb[1][0] = vb[1][1] = 3.4e38f;

    for (int chunk = 0; chunk < 8; ++chunk) {
        float c[2][8][4];
        #pragma unroll
        for (int mi = 0; mi < 2; ++mi)
            #pragma unroll
            for (int nj = 0; nj < 8; ++nj)
                #pragma unroll
                for (int k = 0; k < 4; ++k) c[mi][nj][k] = 0.f;

        for (int kt = 0; kt < 8; ++kt) {
            const int s = chunk * 8 + kt;
            asm volatile("cp.async.wait_group 2;" ::: "memory");
            __syncthreads();
            if (s + 3 < 64) issueB(s + 3);
            asm volatile("cp.async.commit_group;" ::: "memory");

            const unsigned Akt = dynb + kt * 16384;
            const unsigned stg = Bbase + (unsigned)(s & 3) * 16384u;
            #pragma unroll
            for (int k0b = 0; k0b < 4; ++k0b) {
                const int colb = k0b * 32 + kh * 16;
                unsigned Af[2][4], Bf[4][4];
                #pragma unroll
                for (int mi = 0; mi < 2; ++mi)
                    ldsm4(Af[mi], Akt + aRow[mi] + (colb ^ aSw[mi]));
                #pragma unroll
                for (int njp = 0; njp < 4; ++njp)
                    ldsm4(Bf[njp], stg + bRow[njp] + (colb ^ bSw[njp]));
                #pragma unroll
                for (int mi = 0; mi < 2; ++mi)
                    #pragma unroll
                    for (int nj = 0; nj < 8; ++nj)
                        mma16816(c[mi][nj], Af[mi],
                                 Bf[nj >> 1][nj & 1], Bf[nj >> 1][2 + (nj & 1)]);
            }
            __syncthreads();
        }

        // write coarse distances + track per-row min (same fmaf values)
        const float* __restrict__ enp = g_enorm + q * NK + chunk * 128;
        #pragma unroll
        for (int mi = 0; mi < 2; ++mi)
            #pragma unroll
            for (int rh = 0; rh < 2; ++rh) {
                const int row = rowBase + mwBase + mi * 16 + rh * 8 + g;
                float* dst = g_coarse + (size_t)row * NK + chunk * 128;
                #pragma unroll
                for (int nj = 0; nj < 8; ++nj) {
                    const int colL = nwBase + nj * 8 + 2 * tig;
                    float2 d2;
                    d2.x = fmaf(-2.f, c[mi][nj][rh * 2 + 0], enp[colL + 0]);
                    d2.y = fmaf(-2.f, c[mi][nj][rh * 2 + 1], enp[colL + 1]);
                    *reinterpret_cast<float2*>(dst + colL) = d2;
                    vb[mi][rh] = fminf(vb[mi][rh], fminf(d2.x, d2.y));
                }
            }
    }

    // reduce coarse min: over tig lanes, then over nw halves
    #pragma unroll
    for (int mi = 0; mi < 2; ++mi)
        #pragma unroll
        for (int rh = 0; rh < 2; ++rh) {
            float v = vb[mi][rh];
            v = fminf(v, __shfl_xor_sync(0xffffffffu, v, 1));
            v = fminf(v, __shfl_xor_sync(0xffffffffu, v, 2));
            if (tig == 0) sMin[mwBase + mi * 16 + rh * 8 + g][nw] = v;
        }
    __syncthreads();
    if (tid < 128)
        g_cmin[rowBase + tid] = fminf(sMin[tid][0], sMin[tid][1]);
}

// ------------------------- Phase B: rescore + update (warp per row) ----------
__global__ void __launch_bounds__(256) rescore_update_kernel(
    const float* __restrict__ E, float* __restrict__ outF, int q)
{
    __shared__ double sLoss[8];
    const int tid  = threadIdx.x;
    const int lane = tid & 31;
    const int wid  = tid >> 5;
    const int row  = blockIdx.x * 8 + wid;

    const float semax = sqrtf(__int_as_float(g_semax[q]));
    const float thr = g_cmin[row] + 0.022f * sqrtf(g_rnorm[row]) * semax;

    const float4* cd4 = reinterpret_cast<const float4*>(g_coarse + (size_t)row * NK);
    const float4* rp  = reinterpret_cast<const float4*>(g_res + (size_t)row * DIMV);
    float4 ra[4];
    #pragma unroll
    for (int j = 0; j < 4; ++j) ra[j] = rp[lane + 32 * j];

    double bestD = 1.0e300;
    int    bestI = 0x7fffffff;

    #pragma unroll 1
    for (int i = 0; i < 8; ++i) {
        const float4 f4 = cd4[i * 32 + lane];
        unsigned mm[4];
        mm[0] = __ballot_sync(0xffffffffu, f4.x <= thr);
        mm[1] = __ballot_sync(0xffffffffu, f4.y <= thr);
        mm[2] = __ballot_sync(0xffffffffu, f4.z <= thr);
        mm[3] = __ballot_sync(0xffffffffu, f4.w <= thr);
        #pragma unroll
        for (int cc = 0; cc < 4; ++cc) {
            unsigned m = mm[cc];
            while (m) {                         // warp-uniform candidate loop
                const int src = __ffs(m) - 1;
                m &= m - 1;
                const int col = i * 128 + src * 4 + cc;
                // compensated fp32 warp dot: r . E[col]
                const float4* ep =
                    reinterpret_cast<const float4*>(E + (size_t)col * DIMV);
                float s = 0.f, comp = 0.f;
                #pragma unroll
                for (int j = 0; j < 4; ++j) {
                    const float4 b = ep[lane + 32 * j];
                    const float av[4] = {ra[j].x, ra[j].y, ra[j].z, ra[j].w};
                    const float bv[4] = {b.x, b.y, b.z, b.w};
                    #pragma unroll
                    for (int u = 0; u < 4; ++u) {
                        const float p    = av[u] * bv[u];
                        const float perr = fmaf(av[u], bv[u], -p);
                        const float t = s + p;
                        const float z = t - s;
                        const float serr = (s - (t - z)) + (p - z);
                        s = t;
                        comp += serr + perr;
                    }
                }
                #pragma unroll
                for (int off = 16; off > 0; off >>= 1) {
                    s    += __shfl_xor_sync(0xffffffffu, s, off);
                    comp += __shfl_xor_sync(0xffffffffu, comp, off);
                }
                const double dex = (double)g_enorm[q * NK + col]
                                 - 2.0 * ((double)s + (double)comp);
                if (dex < bestD || (dex == bestD && col < bestI)) {
                    bestD = dex; bestI = col;
                }
            }
        }
    }

    // fused update: r -= e[best]; refresh h-limb; norms; index write
    const float4* eb = reinterpret_cast<const float4*>(E + (size_t)bestI * DIMV);
    float4* rw = reinterpret_cast<float4*>(g_res + (size_t)row * DIMV);
    uint2*  hw = reinterpret_cast<uint2*>(g_rh) + (size_t)row * 128;
    float ns = 0.f;
    #pragma unroll
    for (int j = 0; j < 4; ++j) {
        const int li = lane + 32 * j;
        float4 r = ra[j];
        const float4 e = eb[li];
        r.x -= e.x; r.y -= e.y; r.z -= e.z; r.w -= e.w;
        rw[li] = r;
        hw[li] = packh4(r.x, r.y, r.z, r.w);
        ns += r.x*r.x + r.y*r.y + r.z*r.z + r.w*r.w;
    }
    #pragma unroll
    for (int off = 16; off > 0; off >>= 1)
        ns += __shfl_xor_sync(0xffffffffu, ns, off);
    if (lane == 0) {
        g_rnorm[row] = ns;
        sLoss[wid] = (double)ns;
        outF[NDTOT + (size_t)row * NQ + q] = (float)bestI;
    }
    __syncthreads();
    if (tid == 0) {
        double tot = 0.0;
        #pragma unroll
        for (int w = 0; w < 8; ++w) tot += sLoss[w];
        g_loss_part[q * 2048 + blockIdx.x] = tot;
    }
}

// ------------------------- finalize + loss ----------------------------------
__global__ void finalize_kernel(const float* __restrict__ x,
                                float* __restrict__ outF)
{
    const int i = blockIdx.x * blockDim.x + threadIdx.x;
    const float4 xv = reinterpret_cast<const float4*>(x)[i];
    const float4 rv = reinterpret_cast<const float4*>(g_res)[i];
    float4 o;
    o.x = xv.x - rv.x; o.y = xv.y - rv.y;
    o.z = xv.z - rv.z; o.w = xv.w - rv.w;
    reinterpret_cast<float4*>(outF)[i] = o;
}

__global__ void loss_sum_kernel(float* __restrict__ outF) {
    __shared__ double sm[256];
    double s = 0.0;
    for (int k = threadIdx.x; k < NQ * 2048; k += 256) s += g_loss_part[k];
    sm[threadIdx.x] = s;
    __syncthreads();
    for (int st = 128; st > 0; st >>= 1) {
        if (threadIdx.x < st) sm[threadIdx.x] += sm[threadIdx.x + st];
        __syncthreads();
    }
    if (threadIdx.x == 0)
        outF[NDTOT + (size_t)NROWS * NQ] = (float)(2.0 * sm[0] / (double)NDTOT);
}

// ---------------------------------------------------------------------------
extern "C" void kernel_launch(void* const* d_in, const int* in_sizes, int n_in,
                              void* d_out, int out_size)
{
    const float* x   = (const float*)d_in[0];
    const float* emb = (const float*)d_in[1];
    float* outF = (float*)d_out;

    cudaFuncSetAttribute(dist_hh_kernel,
                         cudaFuncAttributeMaxDynamicSharedMemorySize, 197632);

    copy_row_kernel<<<2048, 256>>>(x);
    split_emb_kernel<<<4096, 256>>>(emb);
    enorm_kernel<<<1024, 256>>>(emb);

    for (int q = 0; q < NQ; ++q) {
        const float* Eq = emb + (size_t)q * NK * DIMV;
        dist_hh_kernel<<<128, 256, 197632>>>(q);
        rescore_update_kernel<<<2048, 256>>>(Eq, outF, q);
    }

    finalize_kernel<<<8192, 256>>>(x, outF);
    loss_sum_kernel<<<1, 256>>>(outF);
}

// round 11
// speedup vs baseline: 2.7688x; 1.3847x over previous
#include <cuda_runtime.h>
#include <cuda_bf16.h>

#define NROWS 16384          // B*S
#define DIMV  512
#define NQ    8
#define NK    1024
#define NDTOT (NROWS*DIMV)   // 8388608
#define NETOT (NQ*NK*DIMV)   // 4194304

// ------------------------- device scratch (no allocs) ----------------------
__device__ float  g_res[NDTOT];            // fp32 residual
__device__ float  g_enorm[NQ*NK];          // ||e||^2 fp32
__device__ int    g_semax[NQ];             // max ||e||^2 bits per step
__device__ float  g_rnorm[NROWS];          // per-row ||r||^2 (for margin)
__device__ float  g_cmin[NROWS];           // per-row coarse min
__device__ double g_loss_part[NQ*2048];    // loss partials
__device__ float  g_coarse[(size_t)NROWS*NK];   // coarse distances, 64MB
// bf16 high-limbs only
__device__ uint4  g_rh[NDTOT/8];
__device__ uint4  g_eh[NETOT/8];

// ------------------------- PTX helpers (sm_80-compatible only) --------------
__device__ __forceinline__ unsigned smem_u32(const void* p) {
    unsigned a;
    asm("{ .reg .u64 t; cvta.to.shared.u64 t, %1; cvt.u32.u64 %0, t; }"
        : "=r"(a) : "l"(p));
    return a;
}
__device__ __forceinline__ void ldsm4(unsigned* r, unsigned addr) {
    asm volatile("ldmatrix.sync.aligned.m8n8.x4.shared.b16 {%0,%1,%2,%3}, [%4];"
        : "=r"(r[0]), "=r"(r[1]), "=r"(r[2]), "=r"(r[3]) : "r"(addr));
}
__device__ __forceinline__ void mma16816(float* c, const unsigned* a,
                                         unsigned b0, unsigned b1) {
    asm volatile(
        "mma.sync.aligned.m16n8k16.row.col.f32.bf16.bf16.f32 "
        "{%0,%1,%2,%3}, {%4,%5,%6,%7}, {%8,%9}, {%0,%1,%2,%3};"
        : "+f"(c[0]), "+f"(c[1]), "+f"(c[2]), "+f"(c[3])
        : "r"(a[0]), "r"(a[1]), "r"(a[2]), "r"(a[3]), "r"(b0), "r"(b1));
}
__device__ __forceinline__ unsigned short bf16h(float v) {
    __nv_bfloat16 b = __float2bfloat16(v);
    return *reinterpret_cast<unsigned short*>(&b);
}
__device__ __forceinline__ uint2 packh4(float x, float y, float z, float w) {
    return make_uint2((unsigned)bf16h(x) | ((unsigned)bf16h(y) << 16),
                      (unsigned)bf16h(z) | ((unsigned)bf16h(w) << 16));
}

// ------------------------- setup kernels -------------------------------------
__global__ void copy_row_kernel(const float* __restrict__ x) {
    const int lane = threadIdx.x & 31;
    const int wid  = threadIdx.x >> 5;
    const int row  = blockIdx.x * 8 + wid;
    const float4* xp = reinterpret_cast<const float4*>(x) + (size_t)row * 128;
    float4* rp = reinterpret_cast<float4*>(g_res) + (size_t)row * 128;
    uint2*  hp = reinterpret_cast<uint2*>(g_rh) + (size_t)row * 128;
    float ns = 0.f;
    #pragma unroll
    for (int j = 0; j < 4; ++j) {
        const int li = lane + 32 * j;
        float4 v = xp[li];
        rp[li] = v;
        hp[li] = packh4(v.x, v.y, v.z, v.w);
        ns += v.x*v.x + v.y*v.y + v.z*v.z + v.w*v.w;
    }
    #pragma unroll
    for (int off = 16; off > 0; off >>= 1)
        ns += __shfl_xor_sync(0xffffffffu, ns, off);
    if (lane == 0) g_rnorm[row] = ns;
}

__global__ void split_emb_kernel(const float* __restrict__ emb) {
    int i = blockIdx.x * blockDim.x + threadIdx.x;       // 0..1048575
    float4 v = reinterpret_cast<const float4*>(emb)[i];
    reinterpret_cast<uint2*>(g_eh)[i] = packh4(v.x, v.y, v.z, v.w);
}

__global__ void enorm_kernel(const float* __restrict__ emb) {
    int gwarp = (blockIdx.x * blockDim.x + threadIdx.x) >> 5;  // 0..8191
    int lane  = threadIdx.x & 31;
    const float* e = emb + (size_t)gwarp * DIMV;
    float s = 0.f;
    #pragma unroll
    for (int d = lane; d < DIMV; d += 32) { float v = e[d]; s += v * v; }
    #pragma unroll
    for (int off = 16; off > 0; off >>= 1)
        s += __shfl_down_sync(0xffffffffu, s, off);
    if (lane == 0) {
        g_enorm[gwarp] = s;
        atomicMax(&g_semax[gwarp >> 10], __float_as_int(s));   // s > 0
    }
}

// ------------------------- Phase A: hh coarse GEMM + per-row coarse min ------
// 256 CTAs x 256 threads, 2 CTAs/SM. CTA owns 64 rows; A tile 64KB loaded
// once (8 ktiles x 8KB); B streamed through 3-stage 16KB ring, prefetch 2.
// One __syncthreads per k-stage (ring safety proven by program order).
__global__ void __launch_bounds__(256, 2) dist_hh_kernel(int q) {
    extern __shared__ __align__(16) char dsm_raw[];
    __shared__ float sMin[64][4];

    const int tid  = threadIdx.x;
    const int lane = tid & 31;
    const int wid  = tid >> 5;
    const int mw = wid & 1, nw = wid >> 1;        // 2(M) x 4(N) warp grid
    const int rowBase = blockIdx.x << 6;          // 64 rows per CTA

    unsigned rawb = smem_u32(dsm_raw);
    unsigned dynb = (rawb + 127u) & ~127u;        // 128B align (swizzle-safe)
    const unsigned Bbase = dynb + 65536u;

    const int g = lane >> 2, tig = lane & 3;
    const int rlo = lane & 15, kh = lane >> 4;
    const int mwBase = mw * 32, nwBase = nw * 32;
    const int aSw[2] = { ((mwBase +  0 + rlo) & 7) << 4,
                         ((mwBase + 16 + rlo) & 7) << 4 };
    const int bSw[2] = { ((nwBase +  0 + rlo) & 7) << 4,
                         ((nwBase + 16 + rlo) & 7) << 4 };
    const int aRow[2] = { (mwBase +  0 + rlo) * 128, (mwBase + 16 + rlo) * 128 };
    const int bRow[2] = { (nwBase +  0 + rlo) * 128, (nwBase + 16 + rlo) * 128 };

    // ---- load A (64 rows' hh limbs): 8 ktiles x 8KB ----
    #pragma unroll
    for (int j = 0; j < 16; ++j) {
        const int u = tid + (j << 8);                 // 0..4095 (16B units)
        const int kt = u >> 9, within = u & 511;
        const int row = within >> 3, seg = within & 7;
        const uint4* src = g_rh + (size_t)(rowBase + row) * 64 + kt * 8 + seg;
        const unsigned dst = dynb + kt * 8192 + row * 128
                           + ((seg * 16) ^ ((row & 7) << 4));
        asm volatile("cp.async.cg.shared.global [%0], [%1], 16;"
                     :: "r"(dst), "l"(src));
    }
    asm volatile("cp.async.commit_group;" ::: "memory");

    const int ebase = q * NK;
    auto issueB = [&](int s) {
        const int chunkI = s >> 3, ktI = s & 7;
        const unsigned buf = Bbase + (unsigned)(s % 3) * 16384u;
        #pragma unroll
        for (int j = 0; j < 4; ++j) {
            const int u = tid + (j << 8);             // 0..1023
            const int row = u >> 3, seg = u & 7;
            const uint4* src = g_eh + (size_t)(ebase + chunkI * 128 + row) * 64
                             + ktI * 8 + seg;
            const unsigned dst = buf + row * 128
                               + ((seg * 16) ^ ((row & 7) << 4));
            asm volatile("cp.async.cg.shared.global [%0], [%1], 16;"
                         :: "r"(dst), "l"(src));
        }
    };
    issueB(0);
    asm volatile("cp.async.commit_group;" ::: "memory");
    issueB(1);
    asm volatile("cp.async.commit_group;" ::: "memory");

    float vb[2][2];
    vb[0][0] = vb[0][1] = vb[1][0] = vb[1][1] = 3.4e38f;

    for (int chunk = 0; chunk < 8; ++chunk) {
        float c[2][4][4];
        #pragma unroll
        for (int mi = 0; mi < 2; ++mi)
            #pragma unroll
            for (int nj = 0; nj < 4; ++nj)
                #pragma unroll
                for (int k = 0; k < 4; ++k) c[mi][nj][k] = 0.f;

        for (int kt = 0; kt < 8; ++kt) {
            const int s = chunk * 8 + kt;
            // stage s complete: newest outstanding group is B(s+1), except tail
            if (s == 63) asm volatile("cp.async.wait_group 0;" ::: "memory");
            else         asm volatile("cp.async.wait_group 1;" ::: "memory");
            __syncthreads();
            // overwrites buffer of stage s-1, whose compute preceded this sync
            if (s + 2 < 64) {
                issueB(s + 2);
                asm volatile("cp.async.commit_group;" ::: "memory");
            }

            const unsigned Akt = dynb + kt * 8192;
            const unsigned stg = Bbase + (unsigned)(s % 3) * 16384u;
            #pragma unroll
            for (int k0b = 0; k0b < 4; ++k0b) {
                const int colb = k0b * 32 + kh * 16;
                unsigned Af[2][4], Bf[2][4];
                #pragma unroll
                for (int mi = 0; mi < 2; ++mi)
                    ldsm4(Af[mi], Akt + aRow[mi] + (colb ^ aSw[mi]));
                #pragma unroll
                for (int njp = 0; njp < 2; ++njp)
                    ldsm4(Bf[njp], stg + bRow[njp] + (colb ^ bSw[njp]));
                #pragma unroll
                for (int mi = 0; mi < 2; ++mi)
                    #pragma unroll
                    for (int nj = 0; nj < 4; ++nj)
                        mma16816(c[mi][nj], Af[mi],
                                 Bf[nj >> 1][nj & 1], Bf[nj >> 1][2 + (nj & 1)]);
            }
        }

        // write coarse distances + track per-row min (same fmaf values)
        const float* __restrict__ enp = g_enorm + q * NK + chunk * 128;
        #pragma unroll
        for (int mi = 0; mi < 2; ++mi)
            #pragma unroll
            for (int rh = 0; rh < 2; ++rh) {
                const int row = rowBase + mwBase + mi * 16 + rh * 8 + g;
                float* dst = g_coarse + (size_t)row * NK + chunk * 128;
                #pragma unroll
                for (int nj = 0; nj < 4; ++nj) {
                    const int colL = nwBase + nj * 8 + 2 * tig;
                    float2 d2;
                    d2.x = fmaf(-2.f, c[mi][nj][rh * 2 + 0], enp[colL + 0]);
                    d2.y = fmaf(-2.f, c[mi][nj][rh * 2 + 1], enp[colL + 1]);
                    *reinterpret_cast<float2*>(dst + colL) = d2;
                    vb[mi][rh] = fminf(vb[mi][rh], fminf(d2.x, d2.y));
                }
            }
    }

    // reduce coarse min: over tig lanes, then over the 4 N-warps
    #pragma unroll
    for (int mi = 0; mi < 2; ++mi)
        #pragma unroll
        for (int rh = 0; rh < 2; ++rh) {
            float v = vb[mi][rh];
            v = fminf(v, __shfl_xor_sync(0xffffffffu, v, 1));
            v = fminf(v, __shfl_xor_sync(0xffffffffu, v, 2));
            if (tig == 0) sMin[mwBase + mi * 16 + rh * 8 + g][nw] = v;
        }
    __syncthreads();
    if (tid < 64)
        g_cmin[rowBase + tid] = fminf(fminf(sMin[tid][0], sMin[tid][1]),
                                      fminf(sMin[tid][2], sMin[tid][3]));
}

// ------------------------- Phase B: rescore + update (warp per row) ----------
__global__ void __launch_bounds__(256) rescore_update_kernel(
    const float* __restrict__ E, float* __restrict__ outF, int q)
{
    __shared__ double sLoss[8];
    const int tid  = threadIdx.x;
    const int lane = tid & 31;
    const int wid  = tid >> 5;
    const int row  = blockIdx.x * 8 + wid;

    const float semax = sqrtf(__int_as_float(g_semax[q]));
    const float thr = g_cmin[row] + 0.022f * sqrtf(g_rnorm[row]) * semax;

    const float4* cd4 = reinterpret_cast<const float4*>(g_coarse + (size_t)row * NK);
    const float4* rp  = reinterpret_cast<const float4*>(g_res + (size_t)row * DIMV);
    float4 ra[4];
    #pragma unroll
    for (int j = 0; j < 4; ++j) ra[j] = rp[lane + 32 * j];

    double bestD = 1.0e300;
    int    bestI = 0x7fffffff;

    #pragma unroll 1
    for (int i = 0; i < 8; ++i) {
        const float4 f4 = cd4[i * 32 + lane];
        unsigned mm[4];
        mm[0] = __ballot_sync(0xffffffffu, f4.x <= thr);
        mm[1] = __ballot_sync(0xffffffffu, f4.y <= thr);
        mm[2] = __ballot_sync(0xffffffffu, f4.z <= thr);
        mm[3] = __ballot_sync(0xffffffffu, f4.w <= thr);
        #pragma unroll
        for (int cc = 0; cc < 4; ++cc) {
            unsigned m = mm[cc];
            while (m) {                         // warp-uniform candidate loop
                const int src = __ffs(m) - 1;
                m &= m - 1;
                const int col = i * 128 + src * 4 + cc;
                // compensated fp32 warp dot: r . E[col]
                const float4* ep =
                    reinterpret_cast<const float4*>(E + (size_t)col * DIMV);
                float s = 0.f, comp = 0.f;
                #pragma unroll
                for (int j = 0; j < 4; ++j) {
                    const float4 b = ep[lane + 32 * j];
                    const float av[4] = {ra[j].x, ra[j].y, ra[j].z, ra[j].w};
                    const float bv[4] = {b.x, b.y, b.z, b.w};
                    #pragma unroll
                    for (int u = 0; u < 4; ++u) {
                        const float p    = av[u] * bv[u];
                        const float perr = fmaf(av[u], bv[u], -p);
                        const float t = s + p;
                        const float z = t - s;
                        const float serr = (s - (t - z)) + (p - z);
                        s = t;
                        comp += serr + perr;
                    }
                }
                #pragma unroll
                for (int off = 16; off > 0; off >>= 1) {
                    s    += __shfl_xor_sync(0xffffffffu, s, off);
                    comp += __shfl_xor_sync(0xffffffffu, comp, off);
                }
                const double dex = (double)g_enorm[q * NK + col]
                                 - 2.0 * ((double)s + (double)comp);
                if (dex < bestD || (dex == bestD && col < bestI)) {
                    bestD = dex; bestI = col;
                }
            }
        }
    }

    // fused update: r -= e[best]; refresh h-limb; norms; index write
    const float4* eb = reinterpret_cast<const float4*>(E + (size_t)bestI * DIMV);
    float4* rw = reinterpret_cast<float4*>(g_res + (size_t)row * DIMV);
    uint2*  hw = reinterpret_cast<uint2*>(g_rh) + (size_t)row * 128;
    float ns = 0.f;
    #pragma unroll
    for (int j = 0; j < 4; ++j) {
        const int li = lane + 32 * j;
        float4 r = ra[j];
        const float4 e = eb[li];
        r.x -= e.x; r.y -= e.y; r.z -= e.z; r.w -= e.w;
        rw[li] = r;
        hw[li] = packh4(r.x, r.y, r.z, r.w);
        ns += r.x*r.x + r.y*r.y + r.z*r.z + r.w*r.w;
    }
    #pragma unroll
    for (int off = 16; off > 0; off >>= 1)
        ns += __shfl_xor_sync(0xffffffffu, ns, off);
    if (lane == 0) {
        g_rnorm[row] = ns;
        sLoss[wid] = (double)ns;
        outF[NDTOT + (size_t)row * NQ + q] = (float)bestI;
    }
    __syncthreads();
    if (tid == 0) {
        double tot = 0.0;
        #pragma unroll
        for (int w = 0; w < 8; ++w) tot += sLoss[w];
        g_loss_part[q * 2048 + blockIdx.x] = tot;
    }
}

// ------------------------- finalize + loss ----------------------------------
__global__ void finalize_kernel(const float* __restrict__ x,
                                float* __restrict__ outF)
{
    const int i = blockIdx.x * blockDim.x + threadIdx.x;
    const float4 xv = reinterpret_cast<const float4*>(x)[i];
    const float4 rv = reinterpret_cast<const float4*>(g_res)[i];
    float4 o;
    o.x = xv.x - rv.x; o.y = xv.y - rv.y;
    o.z = xv.z - rv.z; o.w = xv.w - rv.w;
    reinterpret_cast<float4*>(outF)[i] = o;
}

__global__ void loss_sum_kernel(float* __restrict__ outF) {
    __shared__ double sm[256];
    double s = 0.0;
    for (int k = threadIdx.x; k < NQ * 2048; k += 256) s += g_loss_part[k];
    sm[threadIdx.x] = s;
    __syncthreads();
    for (int st = 128; st > 0; st >>= 1) {
        if (threadIdx.x < st) sm[threadIdx.x] += sm[threadIdx.x + st];
        __syncthreads();
    }
    if (threadIdx.x == 0)
        outF[NDTOT + (size_t)NROWS * NQ] = (float)(2.0 * sm[0] / (double)NDTOT);
}

// ---------------------------------------------------------------------------
extern "C" void kernel_launch(void* const* d_in, const int* in_sizes, int n_in,
                              void* d_out, int out_size)
{
    const float* x   = (const float*)d_in[0];
    const float* emb = (const float*)d_in[1];
    float* outF = (float*)d_out;

    // A 64KB + B ring 3x16KB + 128B align slack
    const int DSM = 65536 + 49152 + 128;
    cudaFuncSetAttribute(dist_hh_kernel,
                         cudaFuncAttributeMaxDynamicSharedMemorySize, DSM);

    copy_row_kernel<<<2048, 256>>>(x);
    split_emb_kernel<<<4096, 256>>>(emb);
    enorm_kernel<<<1024, 256>>>(emb);

    for (int q = 0; q < NQ; ++q) {
        const float* Eq = emb + (size_t)q * NK * DIMV;
        dist_hh_kernel<<<256, 256, DSM>>>(q);
        rescore_update_kernel<<<2048, 256>>>(Eq, outF, q);
    }

    finalize_kernel<<<8192, 256>>>(x, outF);
    loss_sum_kernel<<<1, 256>>>(outF);
}

// round 15
// speedup vs baseline: 3.1836x; 1.1498x over previous
#include <cuda_runtime.h>
#include <cuda_bf16.h>

#define NROWS 16384          // B*S
#define DIMV  512
#define NQ    8
#define NK    1024
#define NDTOT (NROWS*DIMV)   // 8388608
#define NETOT (NQ*NK*DIMV)   // 4194304

// ------------------------- device scratch (no allocs) ----------------------
__device__ float  g_res[NDTOT];            // fp32 residual
__device__ float  g_enorm[NQ*NK];          // ||e||^2 fp32
__device__ int    g_semax[NQ];             // max ||e||^2 bits per step
__device__ float  g_rnorm[NROWS];          // per-row ||r||^2 (for margin)
__device__ float  g_cmin[NROWS];           // per-row coarse min
__device__ double g_loss_part[NQ*2048];    // loss partials
__device__ float  g_coarse[(size_t)NROWS*NK];   // coarse distances, 64MB
// bf16 high-limbs only
__device__ uint4  g_rh[NDTOT/8];
__device__ uint4  g_eh[NETOT/8];

// ------------------------- PTX helpers (sm_80-compatible only) --------------
__device__ __forceinline__ unsigned smem_u32(const void* p) {
    unsigned a;
    asm("{ .reg .u64 t; cvta.to.shared.u64 t, %1; cvt.u32.u64 %0, t; }"
        : "=r"(a) : "l"(p));
    return a;
}
__device__ __forceinline__ void ldsm4(unsigned* r, unsigned addr) {
    asm volatile("ldmatrix.sync.aligned.m8n8.x4.shared.b16 {%0,%1,%2,%3}, [%4];"
        : "=r"(r[0]), "=r"(r[1]), "=r"(r[2]), "=r"(r[3]) : "r"(addr));
}
__device__ __forceinline__ void mma16816(float* c, const unsigned* a,
                                         unsigned b0, unsigned b1) {
    asm volatile(
        "mma.sync.aligned.m16n8k16.row.col.f32.bf16.bf16.f32 "
        "{%0,%1,%2,%3}, {%4,%5,%6,%7}, {%8,%9}, {%0,%1,%2,%3};"
        : "+f"(c[0]), "+f"(c[1]), "+f"(c[2]), "+f"(c[3])
        : "r"(a[0]), "r"(a[1]), "r"(a[2]), "r"(a[3]), "r"(b0), "r"(b1));
}
__device__ __forceinline__ unsigned short bf16h(float v) {
    __nv_bfloat16 b = __float2bfloat16(v);
    return *reinterpret_cast<unsigned short*>(&b);
}
__device__ __forceinline__ uint2 packh4(float x, float y, float z, float w) {
    return make_uint2((unsigned)bf16h(x) | ((unsigned)bf16h(y) << 16),
                      (unsigned)bf16h(z) | ((unsigned)bf16h(w) << 16));
}

// ------------------------- setup kernels -------------------------------------
__global__ void copy_row_kernel(const float* __restrict__ x) {
    const int lane = threadIdx.x & 31;
    const int wid  = threadIdx.x >> 5;
    const int row  = blockIdx.x * 8 + wid;
    const float4* xp = reinterpret_cast<const float4*>(x) + (size_t)row * 128;
    float4* rp = reinterpret_cast<float4*>(g_res) + (size_t)row * 128;
    uint2*  hp = reinterpret_cast<uint2*>(g_rh) + (size_t)row * 128;
    float ns = 0.f;
    #pragma unroll
    for (int j = 0; j < 4; ++j) {
        const int li = lane + 32 * j;
        float4 v = xp[li];
        rp[li] = v;
        hp[li] = packh4(v.x, v.y, v.z, v.w);
        ns += v.x*v.x + v.y*v.y + v.z*v.z + v.w*v.w;
    }
    #pragma unroll
    for (int off = 16; off > 0; off >>= 1)
        ns += __shfl_xor_sync(0xffffffffu, ns, off);
    if (lane == 0) g_rnorm[row] = ns;
}

__global__ void split_emb_kernel(const float* __restrict__ emb) {
    int i = blockIdx.x * blockDim.x + threadIdx.x;       // 0..1048575
    float4 v = reinterpret_cast<const float4*>(emb)[i];
    reinterpret_cast<uint2*>(g_eh)[i] = packh4(v.x, v.y, v.z, v.w);
}

__global__ void enorm_kernel(const float* __restrict__ emb) {
    int gwarp = (blockIdx.x * blockDim.x + threadIdx.x) >> 5;  // 0..8191
    int lane  = threadIdx.x & 31;
    const float* e = emb + (size_t)gwarp * DIMV;
    float s = 0.f;
    #pragma unroll
    for (int d = lane; d < DIMV; d += 32) { float v = e[d]; s += v * v; }
    #pragma unroll
    for (int off = 16; off > 0; off >>= 1)
        s += __shfl_down_sync(0xffffffffu, s, off);
    if (lane == 0) {
        g_enorm[gwarp] = s;
        atomicMax(&g_semax[gwarp >> 10], __float_as_int(s));   // s > 0
    }
}

// ------------------------- Phase A: hh coarse GEMM + per-row coarse min ------
// 256 CTAs x 256 threads, 2 CTAs/SM (96.1KB dyn smem). CTA owns 64 rows;
// A tile 64KB loaded once (8 ktiles x 8KB); B double-buffered 2x16KB,
// prefetch distance 1. One __syncthreads per k-stage.
__global__ void __launch_bounds__(256, 2) dist_hh_kernel(int q) {
    extern __shared__ __align__(16) char dsm_raw[];
    __shared__ float sMin[64][4];

    const int tid  = threadIdx.x;
    const int lane = tid & 31;
    const int wid  = tid >> 5;
    const int mw = wid & 1, nw = wid >> 1;        // 2(M) x 4(N) warp grid
    const int rowBase = blockIdx.x << 6;          // 64 rows per CTA

    unsigned rawb = smem_u32(dsm_raw);
    unsigned dynb = (rawb + 127u) & ~127u;        // 128B align (swizzle-safe)
    const unsigned Bbase = dynb + 65536u;

    const int g = lane >> 2, tig = lane & 3;
    const int rlo = lane & 15, kh = lane >> 4;
    const int mwBase = mw * 32, nwBase = nw * 32;
    const int aSw[2] = { ((mwBase +  0 + rlo) & 7) << 4,
                         ((mwBase + 16 + rlo) & 7) << 4 };
    const int bSw[2] = { ((nwBase +  0 + rlo) & 7) << 4,
                         ((nwBase + 16 + rlo) & 7) << 4 };
    const int aRow[2] = { (mwBase +  0 + rlo) * 128, (mwBase + 16 + rlo) * 128 };
    const int bRow[2] = { (nwBase +  0 + rlo) * 128, (nwBase + 16 + rlo) * 128 };

    // ---- load A (64 rows' hh limbs): 8 ktiles x 8KB ----
    #pragma unroll
    for (int j = 0; j < 16; ++j) {
        const int u = tid + (j << 8);                 // 0..4095 (16B units)
        const int kt = u >> 9, within = u & 511;
        const int row = within >> 3, seg = within & 7;
        const uint4* src = g_rh + (size_t)(rowBase + row) * 64 + kt * 8 + seg;
        const unsigned dst = dynb + kt * 8192 + row * 128
                           + ((seg * 16) ^ ((row & 7) << 4));
        asm volatile("cp.async.cg.shared.global [%0], [%1], 16;"
                     :: "r"(dst), "l"(src));
    }
    asm volatile("cp.async.commit_group;" ::: "memory");

    const int ebase = q * NK;
    auto issueB = [&](int s) {
        const int chunkI = s >> 3, ktI = s & 7;
        const unsigned buf = Bbase + (unsigned)(s & 1) * 16384u;
        #pragma unroll
        for (int j = 0; j < 4; ++j) {
            const int u = tid + (j << 8);             // 0..1023
            const int row = u >> 3, seg = u & 7;
            const uint4* src = g_eh + (size_t)(ebase + chunkI * 128 + row) * 64
                             + ktI * 8 + seg;
            const unsigned dst = buf + row * 128
                               + ((seg * 16) ^ ((row & 7) << 4));
            asm volatile("cp.async.cg.shared.global [%0], [%1], 16;"
                         :: "r"(dst), "l"(src));
        }
    };
    issueB(0);
    asm volatile("cp.async.commit_group;" ::: "memory");

    float vb[2][2];
    vb[0][0] = vb[0][1] = vb[1][0] = vb[1][1] = 3.4e38f;

    for (int chunk = 0; chunk < 8; ++chunk) {
        float c[2][4][4];
        #pragma unroll
        for (int mi = 0; mi < 2; ++mi)
            #pragma unroll
            for (int nj = 0; nj < 4; ++nj)
                #pragma unroll
                for (int k = 0; k < 4; ++k) c[mi][nj][k] = 0.f;

        for (int kt = 0; kt < 8; ++kt) {
            const int s = chunk * 8 + kt;
            // B(s) is the newest outstanding group; wait for it (and A at s=0)
            asm volatile("cp.async.wait_group 0;" ::: "memory");
            __syncthreads();
            // prefetch B(s+1): overwrites buffer of stage s-1, whose compute
            // preceded this sync in program order for every thread
            if (s + 1 < 64) {
                issueB(s + 1);
                asm volatile("cp.async.commit_group;" ::: "memory");
            }

            const unsigned Akt = dynb + kt * 8192;
            const unsigned stg = Bbase + (unsigned)(s & 1) * 16384u;
            #pragma unroll
            for (int k0b = 0; k0b < 4; ++k0b) {
                const int colb = k0b * 32 + kh * 16;
                unsigned Af[2][4], Bf[2][4];
                #pragma unroll
                for (int mi = 0; mi < 2; ++mi)
                    ldsm4(Af[mi], Akt + aRow[mi] + (colb ^ aSw[mi]));
                #pragma unroll
                for (int njp = 0; njp < 2; ++njp)
                    ldsm4(Bf[njp], stg + bRow[njp] + (colb ^ bSw[njp]));
                #pragma unroll
                for (int mi = 0; mi < 2; ++mi)
                    #pragma unroll
                    for (int nj = 0; nj < 4; ++nj)
                        mma16816(c[mi][nj], Af[mi],
                                 Bf[nj >> 1][nj & 1], Bf[nj >> 1][2 + (nj & 1)]);
            }
        }

        // write coarse distances + track per-row min (same fmaf values)
        const float* __restrict__ enp = g_enorm + q * NK + chunk * 128;
        #pragma unroll
        for (int mi = 0; mi < 2; ++mi)
            #pragma unroll
            for (int rh = 0; rh < 2; ++rh) {
                const int row = rowBase + mwBase + mi * 16 + rh * 8 + g;
                float* dst = g_coarse + (size_t)row * NK + chunk * 128;
                #pragma unroll
                for (int nj = 0; nj < 4; ++nj) {
                    const int colL = nwBase + nj * 8 + 2 * tig;
                    float2 d2;
                    d2.x = fmaf(-2.f, c[mi][nj][rh * 2 + 0], enp[colL + 0]);
                    d2.y = fmaf(-2.f, c[mi][nj][rh * 2 + 1], enp[colL + 1]);
                    *reinterpret_cast<float2*>(dst + colL) = d2;
                    vb[mi][rh] = fminf(vb[mi][rh], fminf(d2.x, d2.y));
                }
            }
    }

    // reduce coarse min: over tig lanes, then over the 4 N-warps
    #pragma unroll
    for (int mi = 0; mi < 2; ++mi)
        #pragma unroll
        for (int rh = 0; rh < 2; ++rh) {
            float v = vb[mi][rh];
            v = fminf(v, __shfl_xor_sync(0xffffffffu, v, 1));
            v = fminf(v, __shfl_xor_sync(0xffffffffu, v, 2));
            if (tig == 0) sMin[mwBase + mi * 16 + rh * 8 + g][nw] = v;
        }
    __syncthreads();
    if (tid < 64)
        g_cmin[rowBase + tid] = fminf(fminf(sMin[tid][0], sMin[tid][1]),
                                      fminf(sMin[tid][2], sMin[tid][3]));
}

// ------------------------- Phase B: rescore + update (warp per row) ----------
__global__ void __launch_bounds__(256) rescore_update_kernel(
    const float* __restrict__ E, float* __restrict__ outF, int q)
{
    __shared__ double sLoss[8];
    const int tid  = threadIdx.x;
    const int lane = tid & 31;
    const int wid  = tid >> 5;
    const int row  = blockIdx.x * 8 + wid;

    const float semax = sqrtf(__int_as_float(g_semax[q]));
    const float thr = g_cmin[row] + 0.022f * sqrtf(g_rnorm[row]) * semax;

    const float4* cd4 = reinterpret_cast<const float4*>(g_coarse + (size_t)row * NK);
    const float4* rp  = reinterpret_cast<const float4*>(g_res + (size_t)row * DIMV);
    float4 ra[4];
    #pragma unroll
    for (int j = 0; j < 4; ++j) ra[j] = rp[lane + 32 * j];

    double bestD = 1.0e300;
    int    bestI = 0x7fffffff;

    #pragma unroll 1
    for (int i = 0; i < 8; ++i) {
        const float4 f4 = cd4[i * 32 + lane];
        unsigned mm[4];
        mm[0] = __ballot_sync(0xffffffffu, f4.x <= thr);
        mm[1] = __ballot_sync(0xffffffffu, f4.y <= thr);
        mm[2] = __ballot_sync(0xffffffffu, f4.z <= thr);
        mm[3] = __ballot_sync(0xffffffffu, f4.w <= thr);
        #pragma unroll
        for (int cc = 0; cc < 4; ++cc) {
            unsigned m = mm[cc];
            while (m) {                         // warp-uniform candidate loop
                const int src = __ffs(m) - 1;
                m &= m - 1;
                const int col = i * 128 + src * 4 + cc;
                // compensated fp32 warp dot: r . E[col]
                const float4* ep =
                    reinterpret_cast<const float4*>(E + (size_t)col * DIMV);
                float s = 0.f, comp = 0.f;
                #pragma unroll
                for (int j = 0; j < 4; ++j) {
                    const float4 b = ep[lane + 32 * j];
                    const float av[4] = {ra[j].x, ra[j].y, ra[j].z, ra[j].w};
                    const float bv[4] = {b.x, b.y, b.z, b.w};
                    #pragma unroll
                    for (int u = 0; u < 4; ++u) {
                        const float p    = av[u] * bv[u];
                        const float perr = fmaf(av[u], bv[u], -p);
                        const float t = s + p;
                        const float z = t - s;
                        const float serr = (s - (t - z)) + (p - z);
                        s = t;
                        comp += serr + perr;
                    }
                }
                #pragma unroll
                for (int off = 16; off > 0; off >>= 1) {
                    s    += __shfl_xor_sync(0xffffffffu, s, off);
                    comp += __shfl_xor_sync(0xffffffffu, comp, off);
                }
                const double dex = (double)g_enorm[q * NK + col]
                                 - 2.0 * ((double)s + (double)comp);
                if (dex < bestD || (dex == bestD && col < bestI)) {
                    bestD = dex; bestI = col;
                }
            }
        }
    }

    // fused update: r -= e[best]; refresh h-limb; norms; index write
    const float4* eb = reinterpret_cast<const float4*>(E + (size_t)bestI * DIMV);
    float4* rw = reinterpret_cast<float4*>(g_res + (size_t)row * DIMV);
    uint2*  hw = reinterpret_cast<uint2*>(g_rh) + (size_t)row * 128;
    float ns = 0.f;
    #pragma unroll
    for (int j = 0; j < 4; ++j) {
        const int li = lane + 32 * j;
        float4 r = ra[j];
        const float4 e = eb[li];
        r.x -= e.x; r.y -= e.y; r.z -= e.z; r.w -= e.w;
        rw[li] = r;
        hw[li] = packh4(r.x, r.y, r.z, r.w);
        ns += r.x*r.x + r.y*r.y + r.z*r.z + r.w*r.w;
    }
    #pragma unroll
    for (int off = 16; off > 0; off >>= 1)
        ns += __shfl_xor_sync(0xffffffffu, ns, off);
    if (lane == 0) {
        g_rnorm[row] = ns;
        sLoss[wid] = (double)ns;
        outF[NDTOT + (size_t)row * NQ + q] = (float)bestI;
    }
    __syncthreads();
    if (tid == 0) {
        double tot = 0.0;
        #pragma unroll
        for (int w = 0; w < 8; ++w) tot += sLoss[w];
        g_loss_part[q * 2048 + blockIdx.x] = tot;
    }
}

// ------------------------- finalize + loss ----------------------------------
__global__ void finalize_kernel(const float* __restrict__ x,
                                float* __restrict__ outF)
{
    const int i = blockIdx.x * blockDim.x + threadIdx.x;
    const float4 xv = reinterpret_cast<const float4*>(x)[i];
    const float4 rv = reinterpret_cast<const float4*>(g_res)[i];
    float4 o;
    o.x = xv.x - rv.x; o.y = xv.y - rv.y;
    o.z = xv.z - rv.z; o.w = xv.w - rv.w;
    reinterpret_cast<float4*>(outF)[i] = o;
}

__global__ void loss_sum_kernel(float* __restrict__ outF) {
    __shared__ double sm[256];
    double s = 0.0;
    for (int k = threadIdx.x; k < NQ * 2048; k += 256) s += g_loss_part[k];
    sm[threadIdx.x] = s;
    __syncthreads();
    for (int st = 128; st > 0; st >>= 1) {
        if (threadIdx.x < st) sm[threadIdx.x] += sm[threadIdx.x + st];
        __syncthreads();
    }
    if (threadIdx.x == 0)
        outF[NDTOT + (size_t)NROWS * NQ] = (float)(2.0 * sm[0] / (double)NDTOT);
}

// ---------------------------------------------------------------------------
extern "C" void kernel_launch(void* const* d_in, const int* in_sizes, int n_in,
                              void* d_out, int out_size)
{
    const float* x   = (const float*)d_in[0];
    const float* emb = (const float*)d_in[1];
    float* outF = (float*)d_out;

    // A 64KB + B ring 2x16KB + 128B align slack = 96.1KB -> 2 CTAs/SM
    const int DSM = 65536 + 32768 + 128;
    cudaFuncSetAttribute(dist_hh_kernel,
                         cudaFuncAttributeMaxDynamicSharedMemorySize, DSM);

    copy_row_kernel<<<2048, 256>>>(x);
    split_emb_kernel<<<4096, 256>>>(emb);
    enorm_kernel<<<1024, 256>>>(emb);

    for (int q = 0; q < NQ; ++q) {
        const float* Eq = emb + (size_t)q * NK * DIMV;
        dist_hh_kernel<<<256, 256, DSM>>>(q);
        rescore_update_kernel<<<2048, 256>>>(Eq, outF, q);
    }

    finalize_kernel<<<8192, 256>>>(x, outF);
    loss_sum_kernel<<<1, 256>>>(outF);
}